// round 1
// baseline (speedup 1.0000x reference)
#include <cuda_runtime.h>

#define NTHREADS 256
#define DIM_NX 64
#define DIM_NQ 64
#define DIM_NU 16
#define XS_STRIDE 65   // pad to kill 32-way bank conflicts on per-row access
#define US_STRIDE 17

// SMEM float counts
// C1T 4096 | D12T 1024 | D11 4096 | AT 4096 | B1T 4096 | B2T 1024 | bv 64 | bx 64
// xs 256*65 | us 256*17 | ws 256*65
#define SMEM_FLOATS (4096*4 + 1024*2 + 128 + NTHREADS*XS_STRIDE*2 + NTHREADS*US_STRIDE)

__global__ void __launch_bounds__(NTHREADS)
renl2_kernel(const float* __restrict__ gx,  const float* __restrict__ gu,
             const float* __restrict__ gA,  const float* __restrict__ gB1,
             const float* __restrict__ gB2, const float* __restrict__ gC1,
             const float* __restrict__ gD11,const float* __restrict__ gD12,
             const float* __restrict__ gbv, const float* __restrict__ gbx,
             float* __restrict__ gout)
{
    extern __shared__ float sm[];
    float* sC1T  = sm;                 // [j][i] = C1[i][j]
    float* sD12T = sC1T  + 4096;       // [k][i] = D12[i][k]
    float* sD11  = sD12T + 1024;       // row-major, as-is
    float* sAT   = sD11  + 4096;       // [j][k] = A[k][j]
    float* sB1T  = sAT   + 4096;       // [j][k] = B1[k][j]
    float* sB2T  = sB1T  + 4096;       // [j][k] = B2[k][j]
    float* sbv   = sB2T  + 1024;
    float* sbx   = sbv   + 64;
    float* xs    = sbx   + 64;                       // [256][65]
    float* us    = xs    + NTHREADS * XS_STRIDE;     // [256][17]
    float* ws    = us    + NTHREADS * US_STRIDE;     // [256][65]

    const int tid     = threadIdx.x;
    const int rowbase = blockIdx.x * NTHREADS;

    // ---- stage matrices (transpose on the fly; one-time, conflicts irrelevant)
    for (int idx = tid; idx < 4096; idx += NTHREADS) {
        const int i = idx >> 6, j = idx & 63;
        sC1T[j * 64 + i] = gC1[idx];
        sD11[idx]        = gD11[idx];
        sAT [j * 64 + i] = gA [idx];
        sB1T[j * 64 + i] = gB1[idx];
    }
    for (int idx = tid; idx < 1024; idx += NTHREADS) {
        const int i = idx >> 4, k = idx & 15;
        sD12T[k * 64 + i] = gD12[idx];
        sB2T [k * 64 + i] = gB2 [idx];
    }
    if (tid < 64) { sbv[tid] = gbv[tid]; sbx[tid] = gbx[tid]; }

    // ---- stage x, u tiles (coalesced float4 global reads)
    const float4* gx4 = reinterpret_cast<const float4*>(gx + (size_t)rowbase * DIM_NX);
    #pragma unroll 1
    for (int idx4 = tid; idx4 < NTHREADS * DIM_NX / 4; idx4 += NTHREADS) {
        const float4 v = gx4[idx4];
        const int r = idx4 >> 4, c = (idx4 & 15) << 2;
        float* p = &xs[r * XS_STRIDE + c];
        p[0] = v.x; p[1] = v.y; p[2] = v.z; p[3] = v.w;
    }
    const float4* gu4 = reinterpret_cast<const float4*>(gu + (size_t)rowbase * DIM_NU);
    #pragma unroll 1
    for (int idx4 = tid; idx4 < NTHREADS * DIM_NU / 4; idx4 += NTHREADS) {
        const float4 v = gu4[idx4];
        const int r = idx4 >> 2, c = (idx4 & 3) << 2;
        float* p = &us[r * US_STRIDE + c];
        p[0] = v.x; p[1] = v.y; p[2] = v.z; p[3] = v.w;
    }
    __syncthreads();

    const float* myx = &xs[tid * XS_STRIDE];
    const float* myu = &us[tid * US_STRIDE];

    // ================= phase 1: base  (w[i] = bv[i] + C1[i,:]x + D12[i,:]u)
    float w[DIM_NQ];
    #pragma unroll
    for (int i = 0; i < DIM_NQ; i++) w[i] = sbv[i];

    #pragma unroll 2
    for (int j = 0; j < DIM_NX; j++) {
        const float xj = myx[j];
        const float4* crow = reinterpret_cast<const float4*>(&sC1T[j * 64]);
        #pragma unroll
        for (int q = 0; q < 16; q++) {
            const float4 c = crow[q];
            w[4*q+0] = fmaf(c.x, xj, w[4*q+0]);
            w[4*q+1] = fmaf(c.y, xj, w[4*q+1]);
            w[4*q+2] = fmaf(c.z, xj, w[4*q+2]);
            w[4*q+3] = fmaf(c.w, xj, w[4*q+3]);
        }
    }
    #pragma unroll 2
    for (int k = 0; k < DIM_NU; k++) {
        const float uk = myu[k];
        const float4* drow = reinterpret_cast<const float4*>(&sD12T[k * 64]);
        #pragma unroll
        for (int q = 0; q < 16; q++) {
            const float4 c = drow[q];
            w[4*q+0] = fmaf(c.x, uk, w[4*q+0]);
            w[4*q+1] = fmaf(c.y, uk, w[4*q+1]);
            w[4*q+2] = fmaf(c.z, uk, w[4*q+2]);
            w[4*q+3] = fmaf(c.w, uk, w[4*q+3]);
        }
    }

    // ================= phase 2: forward substitution with ReLU (fully unrolled)
    w[0] = fmaxf(w[0], 0.0f);
    #pragma unroll
    for (int i = 1; i < DIM_NQ; i++) {
        float acc[4] = { w[i], 0.0f, 0.0f, 0.0f };
        #pragma unroll
        for (int j = 0; j < i; j++) {
            acc[j & 3] = fmaf(sD11[i * 64 + j], w[j], acc[j & 3]);
        }
        w[i] = fmaxf((acc[0] + acc[1]) + (acc[2] + acc[3]), 0.0f);
    }

    // dump w to padded smem so the output phase can index it at runtime
    float* myw = &ws[tid * XS_STRIDE];
    #pragma unroll
    for (int i = 0; i < DIM_NQ; i++) myw[i] = w[i];
    // (same-thread smem write->read: ordered, no sync needed)

    // ================= phase 3: output (out = bx + A x + B1 w + B2 u)
    float out[DIM_NX];
    #pragma unroll
    for (int k = 0; k < DIM_NX; k++) out[k] = sbx[k];

    #pragma unroll 2
    for (int j = 0; j < DIM_NX; j++) {
        const float xj = myx[j];
        const float wj = myw[j];
        const float4* arow  = reinterpret_cast<const float4*>(&sAT [j * 64]);
        const float4* b1row = reinterpret_cast<const float4*>(&sB1T[j * 64]);
        #pragma unroll
        for (int q = 0; q < 16; q++) {
            const float4 a = arow[q];
            const float4 b = b1row[q];
            out[4*q+0] = fmaf(a.x, xj, out[4*q+0]);
            out[4*q+1] = fmaf(a.y, xj, out[4*q+1]);
            out[4*q+2] = fmaf(a.z, xj, out[4*q+2]);
            out[4*q+3] = fmaf(a.w, xj, out[4*q+3]);
            out[4*q+0] = fmaf(b.x, wj, out[4*q+0]);
            out[4*q+1] = fmaf(b.y, wj, out[4*q+1]);
            out[4*q+2] = fmaf(b.z, wj, out[4*q+2]);
            out[4*q+3] = fmaf(b.w, wj, out[4*q+3]);
        }
    }
    #pragma unroll 2
    for (int j = 0; j < DIM_NU; j++) {
        const float uj = myu[j];
        const float4* b2row = reinterpret_cast<const float4*>(&sB2T[j * 64]);
        #pragma unroll
        for (int q = 0; q < 16; q++) {
            const float4 c = b2row[q];
            out[4*q+0] = fmaf(c.x, uj, out[4*q+0]);
            out[4*q+1] = fmaf(c.y, uj, out[4*q+1]);
            out[4*q+2] = fmaf(c.z, uj, out[4*q+2]);
            out[4*q+3] = fmaf(c.w, uj, out[4*q+3]);
        }
    }

    // ---- stage result through xs for fully coalesced global stores
    __syncthreads();   // everyone done reading xs
    float* myo = &xs[tid * XS_STRIDE];
    #pragma unroll
    for (int k = 0; k < DIM_NX; k++) myo[k] = out[k];
    __syncthreads();

    float4* gout4 = reinterpret_cast<float4*>(gout + (size_t)rowbase * DIM_NX);
    #pragma unroll 1
    for (int idx4 = tid; idx4 < NTHREADS * DIM_NX / 4; idx4 += NTHREADS) {
        const int r = idx4 >> 4, c = (idx4 & 15) << 2;
        const float* p = &xs[r * XS_STRIDE + c];
        gout4[idx4] = make_float4(p[0], p[1], p[2], p[3]);
    }
}

extern "C" void kernel_launch(void* const* d_in, const int* in_sizes, int n_in,
                              void* d_out, int out_size) {
    (void)n_in; (void)out_size;
    const float* x   = (const float*)d_in[0];
    const float* u   = (const float*)d_in[1];
    const float* A   = (const float*)d_in[2];
    const float* B1  = (const float*)d_in[3];
    const float* B2  = (const float*)d_in[4];
    const float* C1  = (const float*)d_in[5];
    const float* D11 = (const float*)d_in[6];
    const float* D12 = (const float*)d_in[7];
    const float* bv  = (const float*)d_in[8];
    const float* bx  = (const float*)d_in[9];
    float* out = (float*)d_out;

    const int N = in_sizes[0] / DIM_NX;          // 262144
    const size_t smem_bytes = (size_t)SMEM_FLOATS * sizeof(float);  // ~219.5 KB

    cudaFuncSetAttribute(renl2_kernel,
                         cudaFuncAttributeMaxDynamicSharedMemorySize,
                         (int)smem_bytes);

    renl2_kernel<<<N / NTHREADS, NTHREADS, smem_bytes>>>(
        x, u, A, B1, B2, C1, D11, D12, bv, bx, out);
}